// round 16
// baseline (speedup 1.0000x reference)
#include <cuda_runtime.h>
#include <cstdint>

#define Tn 128
#define Bn 8
#define Sn 512
#define CLUSTER 16
#define ROWS_PER_CTA 32
#define NTHREADS 512
#define NWARPS 16
#define HALF_ROWS 16
#define HALF_FLOATS (HALF_ROWS * Sn)     // 8192 floats = 32 KB
#define HALF_BYTES (HALF_FLOATS * 4)
#define NBUF 6
#define SMEM_DYN (NBUF * HALF_BYTES)     // 196608 B

#define LOG2E 1.4426950408889634f
#define LN2   0.6931471805599453f

__device__ __forceinline__ float ex2f(float x) {
    float y; asm("ex2.approx.ftz.f32 %0, %1;" : "=f"(y) : "f"(x)); return y;
}
__device__ __forceinline__ float lg2f(float x) {
    float y; asm("lg2.approx.ftz.f32 %0, %1;" : "=f"(y) : "f"(x)); return y;
}
__device__ __forceinline__ void mbar_init(uint32_t mb, uint32_t count) {
    asm volatile("mbarrier.init.shared.b64 [%0], %1;" :: "r"(mb), "r"(count) : "memory");
}
__device__ __forceinline__ void mbar_expect_tx(uint32_t mb, uint32_t bytes) {
    asm volatile("mbarrier.arrive.expect_tx.shared.b64 _, [%0], %1;"
                 :: "r"(mb), "r"(bytes) : "memory");
}
__device__ __forceinline__ void bulk_g2s(uint32_t dst, const float* src,
                                         uint32_t bytes, uint32_t mb) {
    asm volatile("cp.async.bulk.shared::cluster.global.mbarrier::complete_tx::bytes "
                 "[%0], [%1], %2, [%3];"
                 :: "r"(dst), "l"((const void*)src), "r"(bytes), "r"(mb) : "memory");
}
// CTA-scope wait (TMA tile barriers)
__device__ __forceinline__ void mbar_wait(uint32_t mb, uint32_t parity) {
    uint32_t done = 0;
    while (!done) {
        asm volatile(
            "{\n\t.reg .pred p;\n\t"
            "mbarrier.try_wait.parity.acquire.cta.shared::cta.b64 p, [%1], %2, 0x989680;\n\t"
            "selp.b32 %0, 1, 0, p;\n\t}"
            : "=r"(done) : "r"(mb), "r"(parity) : "memory");
    }
}
// CLUSTER-scope acquire wait (V exchange: remote stores must become visible)
__device__ __forceinline__ void mbar_wait_cl(uint32_t mb, uint32_t parity) {
    uint32_t done = 0;
    while (!done) {
        asm volatile(
            "{\n\t.reg .pred p;\n\t"
            "mbarrier.try_wait.parity.acquire.cluster.shared::cta.b64 p, [%1], %2, 0x989680;\n\t"
            "selp.b32 %0, 1, 0, p;\n\t}"
            : "=r"(done) : "r"(mb), "r"(parity) : "memory");
    }
}
__device__ __forceinline__ uint32_t mapa32(uint32_t la, uint32_t ctaid) {
    uint32_t ra;
    asm("mapa.shared::cluster.u32 %0, %1, %2;" : "=r"(ra) : "r"(la), "r"(ctaid));
    return ra;
}
__device__ __forceinline__ uint32_t vex_parity(int p) {   // phase p >= 1
    return (uint32_t)(((p - 1) >> 1) & 1);
}

// First half of the tile-(T1) convert: wait for the tile, convert row lr.
#define CONVERT_H1(T1, EN0) do {                                              \
    const int g_  = 2 * (T1) + half;                                          \
    const int bi_ = g_ % NBUF;                                                \
    mbar_wait(tmbar_s + 8u * bi_, (uint32_t)((g_ / NBUF) & 1));               \
    const float4* r0_ = (const float4*)(tiles + bi_ * HALF_FLOATS + lr * Sn); \
    _Pragma("unroll")                                                         \
    for (int c = 0; c < 4; ++c) {                                             \
        float4 ta_ = r0_[c * 32 + lane];                                      \
        EN0[c].x = ex2f(ta_.x * LOG2E); EN0[c].y = ex2f(ta_.y * LOG2E);       \
        EN0[c].z = ex2f(ta_.z * LOG2E); EN0[c].w = ex2f(ta_.w * LOG2E);       \
    }                                                                         \
} while (0)

// Second half: convert row lr+1 (tile already known present from H1).
#define CONVERT_H2(T1, EN1) do {                                              \
    const int g_  = 2 * (T1) + half;                                          \
    const int bi_ = g_ % NBUF;                                                \
    const float4* r1_ = (const float4*)(tiles + bi_ * HALF_FLOATS + (lr + 1) * Sn); \
    _Pragma("unroll")                                                         \
    for (int c = 0; c < 4; ++c) {                                             \
        float4 tb_ = r1_[c * 32 + lane];                                      \
        EN1[c].x = ex2f(tb_.x * LOG2E); EN1[c].y = ex2f(tb_.y * LOG2E);       \
        EN1[c].z = ex2f(tb_.z * LOG2E); EN1[c].w = ex2f(tb_.w * LOG2E);       \
    }                                                                         \
} while (0)

#define STEP(T_, EC0, EC1, EN0, EN1) do {                                     \
    const int t_ = (T_);                                                      \
    if (t_ + 1 < Tn) CONVERT_H1(t_ + 1, EN0);                                 \
    if (t_ > 0) mbar_wait_cl(vex_s + 8u * (uint32_t)(t_ & 1), vex_parity(t_)); \
    const int pb_ = t_ & 1;                                                   \
    const float M_ = Vb[pb_][0];                                              \
    Wsh[tid] = ex2f((Vb[pb_][tid] - M_) * LOG2E);                             \
    __syncthreads();                                                          \
    const float4* w4_ = (const float4*)Wsh;                                   \
    float a0_ = 0.f, a1_ = 0.f, b0_ = 0.f, b1_ = 0.f;                         \
    _Pragma("unroll")                                                         \
    for (int c = 0; c < 4; ++c) {                                             \
        float4 w_ = w4_[c * 32 + lane];                                       \
        a0_ = fmaf(EC0[c].x, w_.x, a0_); a1_ = fmaf(EC0[c].y, w_.y, a1_);     \
        a0_ = fmaf(EC0[c].z, w_.z, a0_); a1_ = fmaf(EC0[c].w, w_.w, a1_);     \
        b0_ = fmaf(EC1[c].x, w_.x, b0_); b1_ = fmaf(EC1[c].y, w_.y, b1_);     \
        b0_ = fmaf(EC1[c].z, w_.z, b0_); b1_ = fmaf(EC1[c].w, w_.w, b1_);     \
    }                                                                         \
    float acc0_ = a0_ + a1_, acc1_ = b0_ + b1_;                               \
    _Pragma("unroll")                                                         \
    for (int o = 16; o > 0; o >>= 1) {                                        \
        acc0_ += __shfl_xor_sync(0xffffffffu, acc0_, o);                      \
        acc1_ += __shfl_xor_sync(0xffffffffu, acc1_, o);                      \
    }                                                                         \
    /* all lanes hold the sums after butterfly; lanes 0-15 store directly */  \
    /* into peer `lane`'s Vb via DSMEM (no bulk engine involved).         */  \
    const float v0_ = fmaf(lg2f(acc0_), LN2, M_);                             \
    const float v1_ = fmaf(lg2f(acc1_), LN2, M_);                             \
    if (lane < CLUSTER)                                                       \
        asm volatile("st.shared::cluster.v2.f32 [%0], {%1, %2};"              \
                     :: "r"(dstv[(t_ + 1) & 1]), "f"(v0_), "f"(v1_)           \
                     : "memory");                                             \
    __syncthreads();   /* all warps' remote stores issued; tiles consumed */  \
    if (wid == 0) {                                                           \
        asm volatile("fence.acq_rel.cluster;" ::: "memory");                  \
        if (lane < CLUSTER)                                                   \
            asm volatile("mbarrier.arrive.release.cluster.shared::cluster.b64 _, [%0];" \
                         :: "r"(vexr[(t_ + 1) & 1]) : "memory");              \
    } else if (wid == 8 && lane == 0 && t_ + 3 < Tn) {                        \
        asm volatile("fence.proxy.async.shared::cta;" ::: "memory");          \
        const int pre_ = t_ + 3;                                              \
        _Pragma("unroll")                                                     \
        for (int h = 0; h < 2; ++h) {                                         \
            const int gg_ = 2 * pre_ + h;                                     \
            const int bb_ = gg_ % NBUF;                                       \
            mbar_expect_tx(tmbar_s + 8u * bb_, HALF_BYTES);                   \
            bulk_g2s(tiles_s + (uint32_t)bb_ * HALF_BYTES,                    \
                     base + (size_t)pre_ * step_stride + (size_t)h * HALF_FLOATS, \
                     HALF_BYTES, tmbar_s + 8u * bb_);                         \
        }                                                                     \
    }                                                                         \
    if (t_ + 1 < Tn) CONVERT_H2(t_ + 1, EN1);                                 \
} while (0)

__global__ void __launch_bounds__(NTHREADS, 1)
viterbi_kernel(const float* __restrict__ theta, float* __restrict__ out)
{
    extern __shared__ float tiles[];
    __shared__ __align__(16) float Vb[2][Sn];
    __shared__ __align__(16) float Wsh[Sn];
    __shared__ float red[NWARPS];
    __shared__ __align__(8) unsigned long long tmbar[NBUF];
    __shared__ __align__(8) unsigned long long vexbar[2];

    const int tid  = threadIdx.x;
    const int lane = tid & 31;
    const int wid  = tid >> 5;
    const int half = wid >> 3;
    const int lr   = 2 * wid - HALF_ROWS * half;

    uint32_t rank;
    asm("mov.u32 %0, %%cluster_ctarank;" : "=r"(rank));
    const int b = blockIdx.x >> 4;

    const size_t step_stride = (size_t)Bn * Sn * Sn;
    const float* base = theta + (size_t)b * Sn * Sn
                              + (size_t)rank * ROWS_PER_CTA * Sn;

    const uint32_t tiles_s = (uint32_t)__cvta_generic_to_shared(tiles);
    const uint32_t tmbar_s = (uint32_t)__cvta_generic_to_shared(&tmbar[0]);
    const uint32_t vex_s   = (uint32_t)__cvta_generic_to_shared(&vexbar[0]);
    const uint32_t vb_s    = (uint32_t)__cvta_generic_to_shared(&Vb[0][0]);

    // Hoisted remote addresses (peer = lane & 15): this warp's 2 V values land
    // at Vb[phase][rank*32 + 2*wid] in every peer; vex mbar per phase.
    uint32_t dstv[2], vexr[2];
    {
        const uint32_t peer = (uint32_t)(lane & 15);
        #pragma unroll
        for (int p = 0; p < 2; ++p) {
            dstv[p] = mapa32(vb_s + (uint32_t)(p * Sn + (int)rank * ROWS_PER_CTA + 2 * wid) * 4u, peer);
            vexr[p] = mapa32(vex_s + 8u * (uint32_t)p, peer);
        }
    }

    Vb[0][tid] = 0.0f;
    if (tid == 0) {
        #pragma unroll
        for (int s = 0; s < NBUF; ++s) mbar_init(tmbar_s + 8u * s, 1);
        mbar_init(vex_s,      CLUSTER);   // one arrive per sender CTA
        mbar_init(vex_s + 8u, CLUSTER);
    }
    __syncthreads();
    asm volatile("fence.proxy.async.shared::cta;" ::: "memory");
    asm volatile("barrier.cluster.arrive.aligned;" ::: "memory");
    asm volatile("barrier.cluster.wait.aligned;"   ::: "memory");

    // prefetch steps 0..2 (all 6 half-buffers)
    if (tid == 0) {
        #pragma unroll
        for (int g = 0; g < 6; ++g) {
            mbar_expect_tx(tmbar_s + 8u * g, HALF_BYTES);
            bulk_g2s(tiles_s + (uint32_t)g * HALF_BYTES,
                     base + (size_t)(g >> 1) * step_stride + (size_t)(g & 1) * HALF_FLOATS,
                     HALF_BYTES, tmbar_s + 8u * g);
        }
    }

    float4 EA0[4], EA1[4], EB0[4], EB1[4];
    CONVERT_H1(0, EA0);
    CONVERT_H2(0, EA1);

    #pragma unroll 1
    for (int t = 0; t < Tn; t += 2) {
        STEP(t,     EA0, EA1, EB0, EB1);
        STEP(t + 1, EB0, EB1, EA0, EA1);
    }

    // drain final-phase arrivals before exit (all warps tracked every vex phase)
    mbar_wait_cl(vex_s + 8u * (uint32_t)(Tn & 1), vex_parity(Tn));

    if (rank == 0) {
        const int fb = Tn & 1;
        const float M = Vb[fb][0];
        float e = ex2f((Vb[fb][tid] - M) * LOG2E);
        #pragma unroll
        for (int o = 16; o > 0; o >>= 1)
            e += __shfl_xor_sync(0xffffffffu, e, o);
        if (lane == 0) red[wid] = e;
        __syncthreads();
        if (tid == 0) {
            float s = 0.f;
            #pragma unroll
            for (int i = 0; i < NWARPS; ++i) s += red[i];
            out[b] = fmaf(lg2f(s), LN2, M);
        }
    }

    asm volatile("barrier.cluster.arrive.aligned;" ::: "memory");
    asm volatile("barrier.cluster.wait.aligned;"   ::: "memory");
}

extern "C" void kernel_launch(void* const* d_in, const int* in_sizes, int n_in,
                              void* d_out, int out_size)
{
    const float* theta = (const float*)d_in[0];
    float* out = (float*)d_out;

    cudaFuncSetAttribute(viterbi_kernel,
                         cudaFuncAttributeMaxDynamicSharedMemorySize, SMEM_DYN);
    cudaFuncSetAttribute(viterbi_kernel,
                         cudaFuncAttributeNonPortableClusterSizeAllowed, 1);

    cudaLaunchConfig_t cfg = {};
    cfg.gridDim = dim3(Bn * CLUSTER, 1, 1);
    cfg.blockDim = dim3(NTHREADS, 1, 1);
    cfg.dynamicSmemBytes = SMEM_DYN;
    cfg.stream = 0;

    cudaLaunchAttribute attrs[1];
    attrs[0].id = cudaLaunchAttributeClusterDimension;
    attrs[0].val.clusterDim.x = CLUSTER;
    attrs[0].val.clusterDim.y = 1;
    attrs[0].val.clusterDim.z = 1;
    cfg.attrs = attrs;
    cfg.numAttrs = 1;

    cudaLaunchKernelEx(&cfg, viterbi_kernel, theta, out);
}

// round 17
// speedup vs baseline: 2.2573x; 2.2573x over previous
#include <cuda_runtime.h>
#include <cstdint>

#define Tn 128
#define Bn 8
#define Sn 512
#define CLUSTER 16
#define ROWS_PER_CTA 32
#define NTHREADS 512
#define NWARPS 16
#define HALF_ROWS 16
#define HALF_FLOATS (HALF_ROWS * Sn)     // 8192 floats = 32 KB
#define HALF_BYTES (HALF_FLOATS * 4)
#define NBUF 6
#define SMEM_DYN (NBUF * HALF_BYTES)     // 196608 B
#define VEX_BYTES (CLUSTER * 128)        // 2048 B per phase

#define LOG2E 1.4426950408889634f
#define LN2   0.6931471805599453f

__device__ __forceinline__ float ex2f(float x) {
    float y; asm("ex2.approx.ftz.f32 %0, %1;" : "=f"(y) : "f"(x)); return y;
}
__device__ __forceinline__ float lg2f(float x) {
    float y; asm("lg2.approx.ftz.f32 %0, %1;" : "=f"(y) : "f"(x)); return y;
}
__device__ __forceinline__ void mbar_init(uint32_t mb, uint32_t count) {
    asm volatile("mbarrier.init.shared.b64 [%0], %1;" :: "r"(mb), "r"(count) : "memory");
}
__device__ __forceinline__ void mbar_expect_tx(uint32_t mb, uint32_t bytes) {
    asm volatile("mbarrier.arrive.expect_tx.shared.b64 _, [%0], %1;"
                 :: "r"(mb), "r"(bytes) : "memory");
}
__device__ __forceinline__ void bulk_g2s(uint32_t dst, const float* src,
                                         uint32_t bytes, uint32_t mb) {
    asm volatile("cp.async.bulk.shared::cluster.global.mbarrier::complete_tx::bytes "
                 "[%0], [%1], %2, [%3];"
                 :: "r"(dst), "l"((const void*)src), "r"(bytes), "r"(mb) : "memory");
}
__device__ __forceinline__ void bulk_s2s(uint32_t dst_cluster, uint32_t src_cta,
                                         uint32_t bytes, uint32_t mb_cluster) {
    asm volatile("cp.async.bulk.shared::cluster.shared::cta.mbarrier::complete_tx::bytes "
                 "[%0], [%1], %2, [%3];"
                 :: "r"(dst_cluster), "r"(src_cta), "r"(bytes), "r"(mb_cluster) : "memory");
}
__device__ __forceinline__ void mbar_wait(uint32_t mb, uint32_t parity) {
    uint32_t done = 0;
    while (!done) {
        asm volatile(
            "{\n\t.reg .pred p;\n\t"
            "mbarrier.try_wait.parity.acquire.cta.shared::cta.b64 p, [%1], %2, 0x989680;\n\t"
            "selp.b32 %0, 1, 0, p;\n\t}"
            : "=r"(done) : "r"(mb), "r"(parity) : "memory");
    }
}
__device__ __forceinline__ uint32_t mapa32(uint32_t la, uint32_t ctaid) {
    uint32_t ra;
    asm("mapa.shared::cluster.u32 %0, %1, %2;" : "=r"(ra) : "r"(la), "r"(ctaid));
    return ra;
}
__device__ __forceinline__ uint32_t vex_parity(int p) {   // phase p >= 1
    return (uint32_t)(((p - 1) >> 1) & 1);
}

// First half of the tile-(T1) convert: wait for the tile, convert row lr.
#define CONVERT_H1(T1, EN0) do {                                              \
    const int g_  = 2 * (T1) + half;                                          \
    const int bi_ = g_ % NBUF;                                                \
    mbar_wait(tmbar_s + 8u * bi_, (uint32_t)((g_ / NBUF) & 1));               \
    const float4* r0_ = (const float4*)(tiles + bi_ * HALF_FLOATS + lr * Sn); \
    _Pragma("unroll")                                                         \
    for (int c = 0; c < 4; ++c) {                                             \
        float4 ta_ = r0_[c * 32 + lane];                                      \
        EN0[c].x = ex2f(ta_.x * LOG2E); EN0[c].y = ex2f(ta_.y * LOG2E);       \
        EN0[c].z = ex2f(ta_.z * LOG2E); EN0[c].w = ex2f(ta_.w * LOG2E);       \
    }                                                                         \
} while (0)

// Second half: convert row lr+1 (tile already known present from H1).
#define CONVERT_H2(T1, EN1) do {                                              \
    const int g_  = 2 * (T1) + half;                                          \
    const int bi_ = g_ % NBUF;                                                \
    const float4* r1_ = (const float4*)(tiles + bi_ * HALF_FLOATS + (lr + 1) * Sn); \
    _Pragma("unroll")                                                         \
    for (int c = 0; c < 4; ++c) {                                             \
        float4 tb_ = r1_[c * 32 + lane];                                      \
        EN1[c].x = ex2f(tb_.x * LOG2E); EN1[c].y = ex2f(tb_.y * LOG2E);       \
        EN1[c].z = ex2f(tb_.z * LOG2E); EN1[c].w = ex2f(tb_.w * LOG2E);       \
    }                                                                         \
} while (0)

// STEP: arm; convert-H1(t+1); wait V(t); PER-LANE W (no block barrier);
// dot; reduce; stage mine; ONE syncthreads; push / refill; convert-H2(t+1).
#define STEP(T_, EC0, EC1, EN0, EN1) do {                                     \
    const int t_ = (T_);                                                      \
    if (tid == 0)                                                             \
        mbar_expect_tx(vex_s + 8u * (uint32_t)((t_ + 1) & 1), VEX_BYTES);     \
    if (t_ + 1 < Tn) CONVERT_H1(t_ + 1, EN0);                                 \
    if (t_ > 0) mbar_wait(vex_s + 8u * (uint32_t)(t_ & 1), vex_parity(t_));   \
    const int pb_ = t_ & 1;                                                   \
    const float M_ = Vb[pb_][0];                                              \
    const float nM_ = -M_ * LOG2E;                                            \
    const float4* vb4_ = (const float4*)Vb[pb_];                              \
    float a0_ = 0.f, a1_ = 0.f, b0_ = 0.f, b1_ = 0.f;                         \
    _Pragma("unroll")                                                         \
    for (int c = 0; c < 4; ++c) {                                             \
        float4 v_ = vb4_[c * 32 + lane];                                      \
        float4 w_;                                                            \
        w_.x = ex2f(fmaf(v_.x, LOG2E, nM_));                                  \
        w_.y = ex2f(fmaf(v_.y, LOG2E, nM_));                                  \
        w_.z = ex2f(fmaf(v_.z, LOG2E, nM_));                                  \
        w_.w = ex2f(fmaf(v_.w, LOG2E, nM_));                                  \
        a0_ = fmaf(EC0[c].x, w_.x, a0_); a1_ = fmaf(EC0[c].y, w_.y, a1_);     \
        a0_ = fmaf(EC0[c].z, w_.z, a0_); a1_ = fmaf(EC0[c].w, w_.w, a1_);     \
        b0_ = fmaf(EC1[c].x, w_.x, b0_); b1_ = fmaf(EC1[c].y, w_.y, b1_);     \
        b0_ = fmaf(EC1[c].z, w_.z, b0_); b1_ = fmaf(EC1[c].w, w_.w, b1_);     \
    }                                                                         \
    float acc0_ = a0_ + a1_, acc1_ = b0_ + b1_;                               \
    _Pragma("unroll")                                                         \
    for (int o = 16; o > 0; o >>= 1) {                                        \
        acc0_ += __shfl_xor_sync(0xffffffffu, acc0_, o);                      \
        acc1_ += __shfl_xor_sync(0xffffffffu, acc1_, o);                      \
    }                                                                         \
    if (lane == 0) {                                                          \
        mine[pb_][2 * wid]     = fmaf(lg2f(acc0_), LN2, M_);                  \
        mine[pb_][2 * wid + 1] = fmaf(lg2f(acc1_), LN2, M_);                  \
    }                                                                         \
    __syncthreads();   /* mine[] complete; buffers of step t fully consumed */ \
    if (wid == 0) {                                                           \
        asm volatile("fence.proxy.async.shared::cta;" ::: "memory");          \
        if (lane < CLUSTER) {                                                 \
            bulk_s2s(dst_r[(t_ + 1) & 1],                                     \
                     mine_s + (uint32_t)pb_ * (ROWS_PER_CTA * 4),             \
                     ROWS_PER_CTA * 4, mb_r[(t_ + 1) & 1]);                   \
        }                                                                     \
    } else if (wid == 8 && lane == 0 && t_ + 3 < Tn) {                        \
        asm volatile("fence.proxy.async.shared::cta;" ::: "memory");          \
        const int pre_ = t_ + 3;                                              \
        _Pragma("unroll")                                                     \
        for (int h = 0; h < 2; ++h) {                                         \
            const int gg_ = 2 * pre_ + h;                                     \
            const int bb_ = gg_ % NBUF;                                       \
            mbar_expect_tx(tmbar_s + 8u * bb_, HALF_BYTES);                   \
            bulk_g2s(tiles_s + (uint32_t)bb_ * HALF_BYTES,                    \
                     base + (size_t)pre_ * step_stride + (size_t)h * HALF_FLOATS, \
                     HALF_BYTES, tmbar_s + 8u * bb_);                         \
        }                                                                     \
    }                                                                         \
    if (t_ + 1 < Tn) CONVERT_H2(t_ + 1, EN1);                                 \
} while (0)

__global__ void __launch_bounds__(NTHREADS, 1)
viterbi_kernel(const float* __restrict__ theta, float* __restrict__ out)
{
    extern __shared__ float tiles[];
    __shared__ __align__(16) float Vb[2][Sn];
    __shared__ __align__(16) float mine[2][ROWS_PER_CTA];
    __shared__ float red[NWARPS];
    __shared__ __align__(8) unsigned long long tmbar[NBUF];
    __shared__ __align__(8) unsigned long long vexbar[2];

    const int tid  = threadIdx.x;
    const int lane = tid & 31;
    const int wid  = tid >> 5;
    const int half = wid >> 3;
    const int lr   = 2 * wid - HALF_ROWS * half;

    uint32_t rank;
    asm("mov.u32 %0, %%cluster_ctarank;" : "=r"(rank));
    const int b = blockIdx.x >> 4;

    const size_t step_stride = (size_t)Bn * Sn * Sn;
    const float* base = theta + (size_t)b * Sn * Sn
                              + (size_t)rank * ROWS_PER_CTA * Sn;

    const uint32_t tiles_s = (uint32_t)__cvta_generic_to_shared(tiles);
    const uint32_t tmbar_s = (uint32_t)__cvta_generic_to_shared(&tmbar[0]);
    const uint32_t vex_s   = (uint32_t)__cvta_generic_to_shared(&vexbar[0]);
    const uint32_t mine_s  = (uint32_t)__cvta_generic_to_shared(&mine[0][0]);
    const uint32_t vb_s    = (uint32_t)__cvta_generic_to_shared(&Vb[0][0]);

    // Hoisted cluster addresses for the per-step push (depend only on phase&1).
    uint32_t dst_r[2], mb_r[2];
    if (wid == 0 && lane < CLUSTER) {
        #pragma unroll
        for (int p = 0; p < 2; ++p) {
            dst_r[p] = mapa32(vb_s + (uint32_t)(p * Sn + (int)rank * ROWS_PER_CTA) * 4u,
                              (uint32_t)lane);
            mb_r[p]  = mapa32(vex_s + 8u * (uint32_t)p, (uint32_t)lane);
        }
    }

    Vb[0][tid] = 0.0f;
    if (tid == 0) {
        #pragma unroll
        for (int s = 0; s < NBUF; ++s) mbar_init(tmbar_s + 8u * s, 1);
        mbar_init(vex_s,      1);
        mbar_init(vex_s + 8u, 1);
    }
    __syncthreads();
    asm volatile("fence.proxy.async.shared::cta;" ::: "memory");
    asm volatile("barrier.cluster.arrive.aligned;" ::: "memory");
    asm volatile("barrier.cluster.wait.aligned;"   ::: "memory");

    // prefetch steps 0..2 (all 6 half-buffers)
    if (tid == 0) {
        #pragma unroll
        for (int g = 0; g < 6; ++g) {
            mbar_expect_tx(tmbar_s + 8u * g, HALF_BYTES);
            bulk_g2s(tiles_s + (uint32_t)g * HALF_BYTES,
                     base + (size_t)(g >> 1) * step_stride + (size_t)(g & 1) * HALF_FLOATS,
                     HALF_BYTES, tmbar_s + 8u * g);
        }
    }

    float4 EA0[4], EA1[4], EB0[4], EB1[4];
    CONVERT_H1(0, EA0);
    CONVERT_H2(0, EA1);

    #pragma unroll 1
    for (int t = 0; t < Tn; t += 2) {
        STEP(t,     EA0, EA1, EB0, EB1);
        STEP(t + 1, EB0, EB1, EA0, EA1);
    }

    // drain final-phase deliveries before exit (all warps tracked every vex phase)
    mbar_wait(vex_s + 8u * (uint32_t)(Tn & 1), vex_parity(Tn));

    if (rank == 0) {
        const int fb = Tn & 1;
        const float M = Vb[fb][0];
        float e = ex2f((Vb[fb][tid] - M) * LOG2E);
        #pragma unroll
        for (int o = 16; o > 0; o >>= 1)
            e += __shfl_xor_sync(0xffffffffu, e, o);
        if (lane == 0) red[wid] = e;
        __syncthreads();
        if (tid == 0) {
            float s = 0.f;
            #pragma unroll
            for (int i = 0; i < NWARPS; ++i) s += red[i];
            out[b] = fmaf(lg2f(s), LN2, M);
        }
    }

    asm volatile("barrier.cluster.arrive.aligned;" ::: "memory");
    asm volatile("barrier.cluster.wait.aligned;"   ::: "memory");
}

extern "C" void kernel_launch(void* const* d_in, const int* in_sizes, int n_in,
                              void* d_out, int out_size)
{
    const float* theta = (const float*)d_in[0];
    float* out = (float*)d_out;

    cudaFuncSetAttribute(viterbi_kernel,
                         cudaFuncAttributeMaxDynamicSharedMemorySize, SMEM_DYN);
    cudaFuncSetAttribute(viterbi_kernel,
                         cudaFuncAttributeNonPortableClusterSizeAllowed, 1);

    cudaLaunchConfig_t cfg = {};
    cfg.gridDim = dim3(Bn * CLUSTER, 1, 1);
    cfg.blockDim = dim3(NTHREADS, 1, 1);
    cfg.dynamicSmemBytes = SMEM_DYN;
    cfg.stream = 0;

    cudaLaunchAttribute attrs[1];
    attrs[0].id = cudaLaunchAttributeClusterDimension;
    attrs[0].val.clusterDim.x = CLUSTER;
    attrs[0].val.clusterDim.y = 1;
    attrs[0].val.clusterDim.z = 1;
    cfg.attrs = attrs;
    cfg.numAttrs = 1;

    cudaLaunchKernelEx(&cfg, viterbi_kernel, theta, out);
}